// round 15
// baseline (speedup 1.0000x reference)
#include <cuda_runtime.h>
#include <cuda_fp16.h>
#include <math.h>

// ---------------------------------------------------------------------------
// GPT-2 124M forward. Single-pass fp16 mma.sync GEMMs (fp32 accum) +
// fused flash-attention. R15: 256x128 block / 64x64 warp tiles on the
// large GEMMs (QKV, FC, lm_head); proj/FC2 keep 128x128.
// B=4, T=1024, C=768, NH=12, HD=64, NL=12, V=50257
// ---------------------------------------------------------------------------

#define BB   4
#define TT   1024
#define BT   4096
#define CC   768
#define C3   2304
#define C4   3072
#define NHH  12
#define HDD  64
#define NLYR 12
#define VV   50257
#define BHN  48

typedef __half h16;

// fp32 scratch
__device__ float g_x  [(size_t)BT * CC];
__device__ float g_nll[BT];
// fp16 activations
__device__ h16 g_h [(size_t)BT * CC];
__device__ h16 g_q [(size_t)BT * C3];
__device__ h16 g_y [(size_t)BT * CC];
__device__ h16 g_f [(size_t)BT * C4];
// fp16 weights
__device__ h16 g_aw[(size_t)NLYR * CC * C3];
__device__ h16 g_pw[(size_t)NLYR * CC * CC];
__device__ h16 g_fw[(size_t)NLYR * CC * C4];
__device__ h16 g_f2[(size_t)NLYR * C4 * CC];
__device__ h16 g_wt[(size_t)VV * CC];

// ---------------------------------------------------------------------------
// helpers
// ---------------------------------------------------------------------------
__device__ __forceinline__ void ldsm_x4(unsigned a, unsigned* r) {
    asm volatile("ldmatrix.sync.aligned.m8n8.x4.shared.b16 {%0,%1,%2,%3},[%4];"
                 : "=r"(r[0]), "=r"(r[1]), "=r"(r[2]), "=r"(r[3]) : "r"(a));
}
__device__ __forceinline__ void ldsm_x4_t(unsigned a, unsigned* r) {
    asm volatile("ldmatrix.sync.aligned.m8n8.x4.trans.shared.b16 {%0,%1,%2,%3},[%4];"
                 : "=r"(r[0]), "=r"(r[1]), "=r"(r[2]), "=r"(r[3]) : "r"(a));
}
__device__ __forceinline__ void mma16816(float* c, const unsigned* a, const unsigned* b) {
    asm volatile("mma.sync.aligned.m16n8k16.row.col.f32.f16.f16.f32 "
                 "{%0,%1,%2,%3},{%4,%5,%6,%7},{%8,%9},{%0,%1,%2,%3};"
                 : "+f"(c[0]), "+f"(c[1]), "+f"(c[2]), "+f"(c[3])
                 : "r"(a[0]), "r"(a[1]), "r"(a[2]), "r"(a[3]), "r"(b[0]), "r"(b[1]));
}
__device__ __forceinline__ float gelu_f(float u) {
    float t = 0.7978845608028654f * (u + 0.044715f * u * u * u);
    return 0.5f * u * (1.f + tanhf(t));
}

// ---------------------------------------------------------------------------
// Tensor-core GEMM, fp16 in, fp32 accumulate, single pass.
//   NT=false: C = A[M,K] @ B[K,N];  NT=true: C = alpha * A[M,K] @ B[N,K]^T
// EPI: 0 f32 *alpha | 1 h16(acc+bias) | 2 h16(gelu(acc+bias))
//      3 f32 acc+bias+R | 4 h16(acc)
// 256 threads, 8 warps, BK=16, reg-staged double buffer. MINB = min CTAs/SM.
// M%BM==0, K%16==0, (NN) N%BN==0; NT N guarded.
// ---------------------------------------------------------------------------
template<int BM, int BN, int WM, int WN, int EPI, bool NT, bool SKIP, int MINB>
__global__ __launch_bounds__(256, MINB)
void gemm_tc(const h16* __restrict__ A, const h16* __restrict__ B,
             const float* __restrict__ bias, const float* __restrict__ R,
             float* __restrict__ Cf, h16* __restrict__ Ch,
             int M, int N, int K, int lda, int ldb, int ldc, float alpha,
             long aO, long aI, long bO, long bI, long cO, long cI, int innerCnt)
{
    constexpr int BK  = 16;
    constexpr int BKP = 24;        // padded k row stride (48B)
    constexpr int BNP = BN + 8;    // NN B row stride
    constexpr int WARPS_N = BN / WN;
    constexpr int MI = WM / 16, NF = WN / 8, NP = NF / 2;
    constexpr int ALD = (BM * BK / 4) / 256;     // uint2 loads per thread
    constexpr int BLD = (BN * BK / 4) / 256;
    static_assert((BM / WM) * (BN / WN) == 8, "8 warps");

    const int m0 = blockIdx.y * BM;
    const int n0 = blockIdx.x * BN;
    if (SKIP && n0 > m0 + BM - 1) return;

    if (innerCnt > 0) {
        int z = blockIdx.z, zo = z / innerCnt, zi = z % innerCnt;
        A += zo * aO + zi * aI;
        B += zo * bO + zi * bI;
        long co = zo * cO + zi * cI;
        if (Cf) Cf += co;
        if (Ch) Ch += co;
    }

    constexpr int ASZ = BM * BKP;                 // els
    constexpr int BSZ = NT ? BN * BKP : BK * BNP;
    __shared__ __align__(16) h16 sm[2 * (ASZ + BSZ)];

    const int tid = threadIdx.x, lane = tid & 31, w = tid >> 5;
    const int wm = w / WARPS_N, wn = w % WARPS_N;

    float acc[MI][NF][4];
#pragma unroll
    for (int i = 0; i < MI; i++)
#pragma unroll
        for (int j = 0; j < NF; j++)
#pragma unroll
            for (int q = 0; q < 4; q++) acc[i][j][q] = 0.f;

    uint2 pa[ALD], pb[BLD];

    auto loadG = [&](int t) {
#pragma unroll
        for (int j = 0; j < ALD; j++) {
            int i = tid + 256 * j;
            int r = i >> 2, kc = (i & 3) * 4;
            pa[j] = *(const uint2*)(A + (size_t)(m0 + r) * lda + t * BK + kc);
        }
#pragma unroll
        for (int j = 0; j < BLD; j++) {
            int i = tid + 256 * j;
            if (NT) {
                int nr = i >> 2, kc = (i & 3) * 4;
                if (n0 + nr < N)
                    pb[j] = *(const uint2*)(B + (size_t)(n0 + nr) * ldb + t * BK + kc);
                else
                    pb[j] = make_uint2(0u, 0u);
            } else {
                int kk = i / (BN / 4), nc = (i % (BN / 4)) * 4;
                pb[j] = *(const uint2*)(B + (size_t)(t * BK + kk) * ldb + n0 + nc);
            }
        }
    };

    auto storeS = [&](int buf) {
        h16* As = sm + buf * (ASZ + BSZ);
        h16* Bs = As + ASZ;
#pragma unroll
        for (int j = 0; j < ALD; j++) {
            int i = tid + 256 * j;
            int r = i >> 2, kc = (i & 3) * 4;
            *(uint2*)&As[r * BKP + kc] = pa[j];
        }
#pragma unroll
        for (int j = 0; j < BLD; j++) {
            int i = tid + 256 * j;
            if (NT) {
                int nr = i >> 2, kc = (i & 3) * 4;
                *(uint2*)&Bs[nr * BKP + kc] = pb[j];
            } else {
                int kk = i / (BN / 4), nc = (i % (BN / 4)) * 4;
                *(uint2*)&Bs[kk * BNP + nc] = pb[j];
            }
        }
    };

    const int nt = K / BK;
    loadG(0);
    storeS(0);
    __syncthreads();

    for (int t = 0; t < nt; t++) {
        const int buf = t & 1;
        if (t + 1 < nt) loadG(t + 1);

        h16* As = sm + buf * (ASZ + BSZ);
        unsigned sA = (unsigned)__cvta_generic_to_shared(As);
        unsigned sB = sA + ASZ * 2;

        unsigned a[MI][4];
        {
            const int arow = lane & 15;
            const int acol = (lane >> 4) * 8;
#pragma unroll
            for (int mi = 0; mi < MI; mi++)
                ldsm_x4(sA + ((wm * WM + mi * 16 + arow) * BKP + acol) * 2, a[mi]);
        }
#pragma unroll
        for (int p = 0; p < NP; p++) {
            unsigned b[4];
            if (NT) {
                const int nrow = (lane & 7) | ((lane >> 4) << 3);
                const int kcol = ((lane >> 3) & 1) * 8;
                ldsm_x4(sB + ((wn * WN + p * 16 + nrow) * BKP + kcol) * 2, b);
            } else {
                const int krow = lane & 15;
                const int ncol = wn * WN + p * 16 + (lane >> 4) * 8;
                ldsm_x4_t(sB + (krow * BNP + ncol) * 2, b);
            }
#pragma unroll
            for (int mi = 0; mi < MI; mi++) {
                mma16816(acc[mi][2 * p],     a[mi], b);
                mma16816(acc[mi][2 * p + 1], a[mi], b + 2);
            }
        }

        if (t + 1 < nt) {
            storeS(buf ^ 1);
            __syncthreads();
        }
    }

    // epilogue
    const int g = lane >> 2, tg = lane & 3;
#pragma unroll
    for (int mi = 0; mi < MI; mi++) {
#pragma unroll
        for (int nf = 0; nf < NF; nf++) {
            int col = n0 + wn * WN + nf * 8 + tg * 2;
#pragma unroll
            for (int h = 0; h < 2; h++) {
                int row = m0 + wm * WM + mi * 16 + g + h * 8;
                float v0 = acc[mi][nf][2 * h];
                float v1 = acc[mi][nf][2 * h + 1];
                if (EPI == 0) {
                    v0 *= alpha; v1 *= alpha;
                    if (col     < N) Cf[(size_t)row * ldc + col]     = v0;
                    if (col + 1 < N) Cf[(size_t)row * ldc + col + 1] = v1;
                } else if (EPI == 3) {
                    size_t o = (size_t)row * ldc + col;
                    Cf[o]     = v0 + bias[col]     + R[o];
                    Cf[o + 1] = v1 + bias[col + 1] + R[o + 1];
                } else {
                    if (EPI == 1 || EPI == 2) { v0 += bias[col]; v1 += bias[col + 1]; }
                    if (EPI == 2) { v0 = gelu_f(v0); v1 = gelu_f(v1); }
                    size_t o = (size_t)row * ldc + col;
                    *(__half2*)&Ch[o] = __floats2half2_rn(v0, v1);
                }
            }
        }
    }
}

// ---------------------------------------------------------------------------
// Fused flash attention (causal). One CTA = 128 Q rows x one (b,h).
// ---------------------------------------------------------------------------
__global__ void flash_attn(const h16* __restrict__ qkv, h16* __restrict__ y)
{
    const int mb = blockIdx.x;
    const int bh = blockIdx.y;
    const int b  = bh / NHH, hh_ = bh % NHH;
    const int m0 = mb * 128;

    const h16* Qg = qkv + (size_t)b * TT * C3 + hh_ * HDD;
    const h16* Kg = Qg + CC;
    const h16* Vg = Qg + 2 * CC;

    __shared__ __align__(16) h16 sK[128 * 72];
    __shared__ __align__(16) h16 sV[128 * 72];

    const int tid = threadIdx.x, lane = tid & 31, w = tid >> 5;
    const int g = lane >> 2, tg = lane & 3;

    for (int i = tid; i < 2048; i += 256) {
        int r = i >> 4, c = (i & 15) * 4;
        *(uint2*)&sK[r * 72 + c] = *(const uint2*)(Qg + (size_t)(m0 + r) * C3 + c);
    }
    __syncthreads();
    unsigned q[4][4];
    {
        unsigned sKa = (unsigned)__cvta_generic_to_shared(sK);
        const int arow = lane & 15;
        const int ac = (lane >> 4) * 8;
#pragma unroll
        for (int kk = 0; kk < 4; kk++)
            ldsm_x4(sKa + ((w * 16 + arow) * 72 + kk * 16 + ac) * 2, q[kk]);
    }

    float o[8][4];
#pragma unroll
    for (int i = 0; i < 8; i++)
#pragma unroll
        for (int e = 0; e < 4; e++) o[i][e] = 0.f;
    float m_r[2] = {-1e30f, -1e30f}, l_r[2] = {0.f, 0.f};

    for (int kb = 0; kb <= mb; kb++) {
        __syncthreads();
        for (int i = tid; i < 2048; i += 256) {
            int r = i >> 4, c = (i & 15) * 4;
            size_t off = (size_t)(kb * 128 + r) * C3 + c;
            *(uint2*)&sK[r * 72 + c] = *(const uint2*)(Kg + off);
            *(uint2*)&sV[r * 72 + c] = *(const uint2*)(Vg + off);
        }
        __syncthreads();

        float s[16][4];
#pragma unroll
        for (int i = 0; i < 16; i++)
#pragma unroll
            for (int e = 0; e < 4; e++) s[i][e] = 0.f;

        unsigned sKa = (unsigned)__cvta_generic_to_shared(sK);
#pragma unroll
        for (int kk = 0; kk < 4; kk++) {
            const int nrow = (lane & 7) | ((lane >> 4) << 3);
            const int kcol = kk * 16 + ((lane >> 3) & 1) * 8;
#pragma unroll
            for (int p = 0; p < 8; p++) {
                unsigned bf[4];
                ldsm_x4(sKa + ((p * 16 + nrow) * 72 + kcol) * 2, bf);
                mma16816(s[2 * p],     q[kk], bf);
                mma16816(s[2 * p + 1], q[kk], bf + 2);
            }
        }

        if (kb == mb) {
            const int rbase = m0 + w * 16 + g;
#pragma unroll
            for (int nf = 0; nf < 16; nf++)
#pragma unroll
                for (int e = 0; e < 4; e++) {
                    int row = rbase + (e >> 1) * 8;
                    int col = kb * 128 + nf * 8 + tg * 2 + (e & 1);
                    s[nf][e] = (col <= row) ? s[nf][e] * 0.125f : -1e30f;
                }
        } else {
#pragma unroll
            for (int nf = 0; nf < 16; nf++)
#pragma unroll
                for (int e = 0; e < 4; e++) s[nf][e] *= 0.125f;
        }

#pragma unroll
        for (int h2 = 0; h2 < 2; h2++) {
            float mx = -1e30f;
#pragma unroll
            for (int nf = 0; nf < 16; nf++)
                mx = fmaxf(mx, fmaxf(s[nf][2 * h2], s[nf][2 * h2 + 1]));
            mx = fmaxf(mx, __shfl_xor_sync(0xffffffffu, mx, 1));
            mx = fmaxf(mx, __shfl_xor_sync(0xffffffffu, mx, 2));
            float mnew = fmaxf(m_r[h2], mx);
            float sf = expf(m_r[h2] - mnew);
            m_r[h2] = mnew;
            l_r[h2] *= sf;
#pragma unroll
            for (int nf = 0; nf < 8; nf++) { o[nf][2 * h2] *= sf; o[nf][2 * h2 + 1] *= sf; }
            float ls = 0.f;
#pragma unroll
            for (int nf = 0; nf < 16; nf++) {
                float p0 = expf(s[nf][2 * h2] - mnew);
                float p1 = expf(s[nf][2 * h2 + 1] - mnew);
                s[nf][2 * h2] = p0; s[nf][2 * h2 + 1] = p1;
                ls += p0 + p1;
            }
            ls += __shfl_xor_sync(0xffffffffu, ls, 1);
            ls += __shfl_xor_sync(0xffffffffu, ls, 2);
            l_r[h2] += ls;
        }

        unsigned sVa = (unsigned)__cvta_generic_to_shared(sV);
#pragma unroll
        for (int kk = 0; kk < 8; kk++) {
            unsigned ap[4];
            __half2 t0 = __floats2half2_rn(s[2 * kk][0],     s[2 * kk][1]);
            __half2 t1 = __floats2half2_rn(s[2 * kk][2],     s[2 * kk][3]);
            __half2 t2 = __floats2half2_rn(s[2 * kk + 1][0], s[2 * kk + 1][1]);
            __half2 t3 = __floats2half2_rn(s[2 * kk + 1][2], s[2 * kk + 1][3]);
            ap[0] = *(unsigned*)&t0; ap[1] = *(unsigned*)&t1;
            ap[2] = *(unsigned*)&t2; ap[3] = *(unsigned*)&t3;
            const int krow = kk * 16 + (lane & 15);
            const int ncol = (lane >> 4) * 8;
#pragma unroll
            for (int po = 0; po < 4; po++) {
                unsigned bf[4];
                ldsm_x4_t(sVa + (krow * 72 + po * 16 + ncol) * 2, bf);
                mma16816(o[2 * po],     ap, bf);
                mma16816(o[2 * po + 1], ap, bf + 2);
            }
        }
    }

#pragma unroll
    for (int h2 = 0; h2 < 2; h2++) {
        float inv = 1.f / l_r[h2];
        int row = m0 + w * 16 + g + h2 * 8;
#pragma unroll
        for (int po = 0; po < 8; po++) {
            int col = hh_ * HDD + po * 8 + tg * 2;
            __half2 hv = __floats2half2_rn(o[po][2 * h2] * inv, o[po][2 * h2 + 1] * inv);
            *(__half2*)&y[(size_t)(b * TT + row) * CC + col] = hv;
        }
    }
}

// ---------------------------------------------------------------------------
__global__ void conv_arr(const float* __restrict__ s, h16* __restrict__ d, long n)
{
    long i = ((long)blockIdx.x * blockDim.x + threadIdx.x) * 4;
    if (i >= n) return;
    float4 v = *(const float4*)(s + i);
    __half2 a = __floats2half2_rn(v.x, v.y);
    __half2 b = __floats2half2_rn(v.z, v.w);
    *(uint2*)(d + i) = make_uint2(*(unsigned*)&a, *(unsigned*)&b);
}

__global__ void layernorm_k(const float* __restrict__ x, const float* __restrict__ g,
                            const float* __restrict__ b, h16* __restrict__ y)
{
    const int row = blockIdx.x;
    const float* xr = x + (size_t)row * CC;
    __shared__ float s1[256], s2[256];
    const int tid = threadIdx.x;
    float a = 0.f, sq = 0.f;
    for (int c = tid; c < CC; c += 256) { float v = xr[c]; a += v; sq += v * v; }
    s1[tid] = a; s2[tid] = sq; __syncthreads();
    for (int s = 128; s > 0; s >>= 1) {
        if (tid < s) { s1[tid] += s1[tid + s]; s2[tid] += s2[tid + s]; }
        __syncthreads();
    }
    const float mean = s1[0] / CC;
    const float var  = s2[0] / CC - mean * mean;
    const float rstd = rsqrtf(var + 1e-5f);
    for (int c = tid; c < CC; c += 256)
        y[(size_t)row * CC + c] = __float2half_rn((xr[c] - mean) * rstd * g[c] + b[c]);
}

__global__ void embed_k(const int* __restrict__ tok, const float* __restrict__ wte,
                        const float* __restrict__ wpe, float* __restrict__ x)
{
    const int idx = blockIdx.x * blockDim.x + threadIdx.x;
    if (idx >= BT * CC) return;
    const int bt = idx / CC, c = idx % CC;
    const int t  = bt % TT;
    x[idx] = wte[(size_t)tok[bt] * CC + c] + wpe[(size_t)t * CC + c];
}

__global__ void nll_k(const float* __restrict__ logits, const int* __restrict__ target,
                      float* __restrict__ nll)
{
    const int bt = blockIdx.x;
    const float* row = logits + (size_t)bt * VV;
    __shared__ float red[256];
    const int tid = threadIdx.x;

    float mx = -1e30f;
    for (int j = tid; j < VV; j += 256) mx = fmaxf(mx, row[j]);
    red[tid] = mx; __syncthreads();
    for (int s = 128; s > 0; s >>= 1) {
        if (tid < s) red[tid] = fmaxf(red[tid], red[tid + s]);
        __syncthreads();
    }
    mx = red[0]; __syncthreads();

    float sum = 0.f;
    for (int j = tid; j < VV; j += 256) sum += expf(row[j] - mx);
    red[tid] = sum; __syncthreads();
    for (int s = 128; s > 0; s >>= 1) {
        if (tid < s) red[tid] += red[tid + s];
        __syncthreads();
    }
    if (tid == 0)
        nll[bt] = logf(red[0]) + mx - row[target[bt]];
}

__global__ void mean_k(const float* __restrict__ nll, float* __restrict__ out)
{
    __shared__ float red[256];
    const int tid = threadIdx.x;
    float s = 0.f;
    for (int i = tid; i < BT; i += 256) s += nll[i];
    red[tid] = s; __syncthreads();
    for (int st = 128; st > 0; st >>= 1) {
        if (tid < st) red[tid] += red[tid + st];
        __syncthreads();
    }
    if (tid == 0) out[0] = red[0] / (float)BT;
}

// ---------------------------------------------------------------------------
// Launch
// ---------------------------------------------------------------------------
extern "C" void kernel_launch(void* const* d_in, const int* in_sizes, int n_in,
                              void* d_out, int out_size)
{
    const int*   tokens = (const int*)  d_in[0];
    const int*   target = (const int*)  d_in[1];
    const float* wte    = (const float*)d_in[2];
    const float* wpe    = (const float*)d_in[3];
    const float* ln1_g  = (const float*)d_in[4];
    const float* ln1_b  = (const float*)d_in[5];
    const float* attn_w = (const float*)d_in[6];
    const float* attn_b = (const float*)d_in[7];
    const float* proj_w = (const float*)d_in[8];
    const float* proj_b = (const float*)d_in[9];
    const float* ln2_g  = (const float*)d_in[10];
    const float* ln2_b  = (const float*)d_in[11];
    const float* fc_w   = (const float*)d_in[12];
    const float* fc_b   = (const float*)d_in[13];
    const float* fc2_w  = (const float*)d_in[14];
    const float* fc2_b  = (const float*)d_in[15];
    const float* lnf_g  = (const float*)d_in[16];
    const float* lnf_b  = (const float*)d_in[17];
    float* out = (float*)d_out;

    float *x, *nll;
    h16 *h, *q, *y, *f, *aw, *pw, *fw, *f2, *wt;
    cudaGetSymbolAddress((void**)&x,   g_x);
    cudaGetSymbolAddress((void**)&nll, g_nll);
    cudaGetSymbolAddress((void**)&h,   g_h);
    cudaGetSymbolAddress((void**)&q,   g_q);
    cudaGetSymbolAddress((void**)&y,   g_y);
    cudaGetSymbolAddress((void**)&f,   g_f);
    cudaGetSymbolAddress((void**)&aw,  g_aw);
    cudaGetSymbolAddress((void**)&pw,  g_pw);
    cudaGetSymbolAddress((void**)&fw,  g_fw);
    cudaGetSymbolAddress((void**)&f2,  g_f2);
    cudaGetSymbolAddress((void**)&wt,  g_wt);

    // convert weights to fp16 (each launch; ~200us)
    {
        long n1 = (long)NLYR * CC * C3;
        long n2 = (long)NLYR * CC * CC;
        long n3 = (long)NLYR * CC * C4;
        long n5 = (long)VV * CC;
        conv_arr<<<(unsigned)((n1/4 + 255)/256), 256>>>(attn_w, aw, n1);
        conv_arr<<<(unsigned)((n2/4 + 255)/256), 256>>>(proj_w, pw, n2);
        conv_arr<<<(unsigned)((n3/4 + 255)/256), 256>>>(fc_w,   fw, n3);
        conv_arr<<<(unsigned)((n3/4 + 255)/256), 256>>>(fc2_w,  f2, n3);
        conv_arr<<<(unsigned)((n5/4 + 255)/256), 256>>>(wte,    wt, n5);
    }

    embed_k<<<(BT * CC + 255) / 256, 256>>>(tokens, wte, wpe, x);

    for (int l = 0; l < NLYR; l++) {
        const h16* law = aw + (size_t)l * CC * C3;
        const h16* lpw = pw + (size_t)l * CC * CC;
        const h16* lfw = fw + (size_t)l * CC * C4;
        const h16* lf2 = f2 + (size_t)l * C4 * CC;
        const float* ab  = attn_b + (size_t)l * C3;
        const float* pb  = proj_b + (size_t)l * CC;
        const float* fb  = fc_b   + (size_t)l * C4;
        const float* f2b = fc2_b  + (size_t)l * CC;

        layernorm_k<<<BT, 256>>>(x, ln1_g + l * CC, ln1_b + l * CC, h);

        // QKV -> fp16 qkv  (big tile)
        gemm_tc<256,128,64,64,1,false,false,1><<<dim3(C3/128, BT/256), 256>>>(
            h, law, ab, nullptr, nullptr, q,
            BT, C3, CC, CC, C3, C3, 1.f, 0,0,0,0,0,0, 0);

        // fused flash attention -> fp16 y
        flash_attn<<<dim3(TT/128, BHN), 256>>>(q, y);

        // x = x + y @ pw + pb   (f32 residual; 128x128 tile, N=768)
        gemm_tc<128,128,32,64,3,false,false,2><<<dim3(CC/128, BT/128), 256>>>(
            y, lpw, pb, x, x, nullptr,
            BT, CC, CC, CC, CC, CC, 1.f, 0,0,0,0,0,0, 0);

        layernorm_k<<<BT, 256>>>(x, ln2_g + l * CC, ln2_b + l * CC, h);

        // fc + gelu -> fp16 fc  (big tile)
        gemm_tc<256,128,64,64,2,false,false,1><<<dim3(C4/128, BT/256), 256>>>(
            h, lfw, fb, nullptr, nullptr, f,
            BT, C4, CC, CC, C4, C4, 1.f, 0,0,0,0,0,0, 0);

        // x = x + fc @ f2w + f2b  (128x128 tile, N=768)
        gemm_tc<128,128,32,64,3,false,false,2><<<dim3(CC/128, BT/128), 256>>>(
            f, lf2, f2b, x, x, nullptr,
            BT, CC, C4, C4, CC, CC, 1.f, 0,0,0,0,0,0, 0);
    }

    layernorm_k<<<BT, 256>>>(x, lnf_g, lnf_b, h);

    // logits = h @ wte^T (f32 out; big tile)
    gemm_tc<256,128,64,64,0,true,false,1><<<dim3((VV + 127) / 128, BT / 256), 256>>>(
        h, wt, nullptr, nullptr, out, nullptr,
        BT, VV, CC, CC, CC, VV, 1.f, 0,0,0,0,0,0, 0);

    nll_k<<<BT, 256>>>(out, target, nll);
    mean_k<<<1, 256>>>(nll, out + (out_size - 1));
}